// round 7
// baseline (speedup 1.0000x reference)
#include <cuda_runtime.h>
#include <cstdint>

#define BB 1024
#define LL 400
#define TMM 150
#define EPSF 1e-5f

// ---------------- scratch (device globals; no allocations allowed) ----------
__device__ float g_xa[(size_t)BB * 3 * LL];        // [B,3,400]
__device__ float g_m0[(size_t)BB * TMM * 3];       // [B,150,3]  (in-place LSTM)
__device__ float g_s0[(size_t)BB * LL * 3];        // [B,400,3]
__device__ float g_a0[(size_t)BB * LL * 3];        // [B,400,3]
__device__ float g_scr[512 * 32];                  // dump target for inactive lanes

// ---------------- helpers ---------------------------------------------------
__device__ __forceinline__ float tanh_(float x) {
    float y;
    asm("tanh.approx.f32 %0, %1;" : "=f"(y) : "f"(x));
    return y;
}
__device__ __forceinline__ float sigm_(float x) {
    return fmaf(0.5f, tanh_(0.5f * x), 0.5f);
}

// ---------------- conv1d + BN(eval) + LeakyReLU -----------------------------
__global__ void k_conv(const float* __restrict__ x,
                       const float* __restrict__ cw, const float* __restrict__ cb,
                       const float* __restrict__ bw, const float* __restrict__ bb,
                       const float* __restrict__ bm, const float* __restrict__ bv) {
    int idx = blockIdx.x * blockDim.x + threadIdx.x;
    if (idx >= BB * LL) return;
    int b = idx / LL, t = idx % LL;
    const float* xb = x + (size_t)b * 3 * LL;
    float in[3][3];
#pragma unroll
    for (int ci = 0; ci < 3; ci++)
#pragma unroll
        for (int k = 0; k < 3; k++) {
            int tt = t + k - 1;
            in[ci][k] = (tt >= 0 && tt < LL) ? xb[ci * LL + tt] : 0.0f;
        }
#pragma unroll
    for (int co = 0; co < 3; co++) {
        float acc = cb[co];
#pragma unroll
        for (int ci = 0; ci < 3; ci++)
#pragma unroll
            for (int k = 0; k < 3; k++)
                acc = fmaf(cw[(co * 3 + ci) * 3 + k], in[ci][k], acc);
        float sc = bw[co] * rsqrtf(bv[co] + EPSF);
        acc = fmaf(acc - bm[co], sc, bb[co]);
        acc = (acc >= 0.0f) ? acc : 0.01f * acc;
        g_xa[((size_t)b * 3 + co) * LL + t] = acc;
    }
}

// ---------------- forward matmul: out[b,t,c] = sum_k xa[b,c,k]*M[b,k,t] -----
__global__ void k_mm_fwd(const float* __restrict__ M, float* __restrict__ out, int T) {
    int b = blockIdx.x;
    __shared__ float sxa[3][LL];
    for (int i = threadIdx.x; i < 3 * LL; i += blockDim.x)
        sxa[i / LL][i % LL] = g_xa[(size_t)b * 3 * LL + i];
    __syncthreads();
    int t = threadIdx.x;
    if (t >= T) return;
    const float* Mb = M + (size_t)b * LL * T + t;
    float a0 = 0.f, a1 = 0.f, a2 = 0.f;
#pragma unroll 8
    for (int k = 0; k < LL; k++) {
        float mv = Mb[(size_t)k * T];
        a0 = fmaf(sxa[0][k], mv, a0);
        a1 = fmaf(sxa[1][k], mv, a1);
        a2 = fmaf(sxa[2][k], mv, a2);
    }
    float* o = out + ((size_t)b * T + t) * 3;
    o[0] = a0; o[1] = a1; o[2] = a2;
}

// ---------------- fused transpose matmul:
// g_a0[b,t,c] = sum_j xm[b,c,j]*main[b,t,j] + sum_k xs[b,c,k]*side[b,t,k] ----
__global__ void k_mm_bwd(const float* __restrict__ xm,   // [B,3,150]
                         const float* __restrict__ xs,   // [B,3,400]
                         const float* __restrict__ M,    // [B,400,150]
                         const float* __restrict__ S) {  // [B,400,400]
    int b = blockIdx.x;
    __shared__ float sm_[3 * 152];
    __shared__ float ss_[3 * LL];
    const float* xmB = xm + (size_t)b * 3 * TMM;
    const float* xsB = xs + (size_t)b * 3 * LL;
    for (int i = threadIdx.x; i < 3 * TMM; i += blockDim.x)
        sm_[(i / TMM) * 152 + (i % TMM)] = xmB[i];
    for (int i = threadIdx.x; i < 3 * LL; i += blockDim.x)
        ss_[i] = xsB[i];
    __syncthreads();
    int t = threadIdx.x;
    if (t >= LL) return;

    float a0 = 0.f, a1 = 0.f, a2 = 0.f;
    const float2* Mr = reinterpret_cast<const float2*>(M + ((size_t)b * LL + t) * TMM);
#pragma unroll 5
    for (int j = 0; j < TMM / 2; j++) {
        float2 v = Mr[j];
        int j0 = 2 * j;
        a0 = fmaf(sm_[0 * 152 + j0], v.x, fmaf(sm_[0 * 152 + j0 + 1], v.y, a0));
        a1 = fmaf(sm_[1 * 152 + j0], v.x, fmaf(sm_[1 * 152 + j0 + 1], v.y, a1));
        a2 = fmaf(sm_[2 * 152 + j0], v.x, fmaf(sm_[2 * 152 + j0 + 1], v.y, a2));
    }
    const float4* Sr = reinterpret_cast<const float4*>(S + ((size_t)b * LL + t) * LL);
#pragma unroll 4
    for (int k = 0; k < LL / 4; k++) {
        float4 v = Sr[k];
        int k0 = 4 * k;
        a0 = fmaf(ss_[k0], v.x, fmaf(ss_[k0 + 1], v.y, fmaf(ss_[k0 + 2], v.z, fmaf(ss_[k0 + 3], v.w, a0))));
        a1 = fmaf(ss_[LL + k0], v.x, fmaf(ss_[LL + k0 + 1], v.y, fmaf(ss_[LL + k0 + 2], v.z, fmaf(ss_[LL + k0 + 3], v.w, a1))));
        a2 = fmaf(ss_[2 * LL + k0], v.x, fmaf(ss_[2 * LL + k0 + 1], v.y, fmaf(ss_[2 * LL + k0 + 2], v.z, fmaf(ss_[2 * LL + k0 + 3], v.w, a2))));
    }
    float* o = g_a0 + ((size_t)b * LL + t) * 3;
    o[0] = a0; o[1] = a1; o[2] = a2;
}

// ---------------- fused 2-layer LSTM, 3 lanes per sequence ------------------
// Branch-free inner loop, fully converged warp:
//  - all stack/sequence selection done with selects before the loop
//  - every lane always stores (inactive lanes -> scratch, stride 0)
//  - x components loaded directly by each lane (L1 broadcast), no x shfls
//  - only 6 shfls/step (h1, h2 exchange); they double as the ordering barrier
//    that makes the in-place prefetch(t+1)-before-store(t+1) pattern safe.
__device__ __forceinline__ void lstm3(const float* __restrict__ Wih,
                                      const float* __restrict__ Whh,
                                      const float* __restrict__ bih,
                                      const float* __restrict__ bhh,
                                      const float* __restrict__ ib,
                                      float* __restrict__ ob, int ostr,
                                      int T, int u, int base) {
    float wi1[4][3], wh1[4][3], b1[4], wi2[4][3], wh2[4][3], b2[4];
#pragma unroll
    for (int q = 0; q < 4; q++) {
        int gi = q * 3 + u;
#pragma unroll
        for (int v = 0; v < 3; v++) {
            wi1[q][v] = Wih[gi * 3 + v];
            wh1[q][v] = Whh[gi * 3 + v];
            wi2[q][v] = Wih[36 + gi * 3 + v];
            wh2[q][v] = Whh[36 + gi * 3 + v];
        }
        b1[q] = bih[gi] + bhh[gi];
        b2[q] = bih[12 + gi] + bhh[12 + gi];
    }

    float c1 = 0.f, c2 = 0.f;
    float h1a = 0.f, h1b = 0.f, h1c = 0.f;
    float h2a = 0.f, h2b = 0.f, h2c = 0.f;

    // prologue: x(0) and its Wih contribution
    float nx0 = ib[0], nx1 = ib[1], nx2 = ib[2];
    float xc[4];
#pragma unroll
    for (int q = 0; q < 4; q++)
        xc[q] = fmaf(nx0, wi1[q][0], fmaf(nx1, wi1[q][1], fmaf(nx2, wi1[q][2], b1[q])));

    for (int t = 0; t < T; t++) {
        // prefetch x(t+1) (clamped, branch-free); ordered before any lane's
        // store to t+1 by the shfl barriers below
        int tn3 = ((t + 1 < T) ? (t + 1) : t) * 3;
        nx0 = ib[tn3]; nx1 = ib[tn3 + 1]; nx2 = ib[tn3 + 2];

        // layer-2 recurrent part (independent of this step's layer-1 output)
        float p2[4];
#pragma unroll
        for (int q = 0; q < 4; q++)
            p2[q] = fmaf(h2a, wh2[q][0], fmaf(h2b, wh2[q][1], fmaf(h2c, wh2[q][2], b2[q])));

        // ---- layer 1 ----
        float g[4];
#pragma unroll
        for (int q = 0; q < 4; q++)
            g[q] = fmaf(h1a, wh1[q][0], fmaf(h1b, wh1[q][1], fmaf(h1c, wh1[q][2], xc[q])));
        float si = sigm_(g[0]), sf = sigm_(g[1]), tg = tanh_(g[2]), so = sigm_(g[3]);
        c1 = fmaf(sf, c1, si * tg);
        float h1u = so * tanh_(c1);
        h1a = __shfl_sync(0xffffffffu, h1u, base);
        h1b = __shfl_sync(0xffffffffu, h1u, base + 1);
        h1c = __shfl_sync(0xffffffffu, h1u, base + 2);

        // next step's x contribution (off the h-chain)
#pragma unroll
        for (int q = 0; q < 4; q++)
            xc[q] = fmaf(nx0, wi1[q][0], fmaf(nx1, wi1[q][1], fmaf(nx2, wi1[q][2], b1[q])));

        // ---- layer 2 ----
#pragma unroll
        for (int q = 0; q < 4; q++)
            g[q] = fmaf(h1a, wi2[q][0], fmaf(h1b, wi2[q][1], fmaf(h1c, wi2[q][2], p2[q])));
        float si2 = sigm_(g[0]), sf2 = sigm_(g[1]), tg2 = tanh_(g[2]), so2 = sigm_(g[3]);
        c2 = fmaf(sf2, c2, si2 * tg2);
        float h2u = so2 * tanh_(c2);
        h2a = __shfl_sync(0xffffffffu, h2u, base);
        h2b = __shfl_sync(0xffffffffu, h2u, base + 1);
        h2c = __shfl_sync(0xffffffffu, h2u, base + 2);

        ob[t * ostr] = h2u;   // unconditional (inactive lanes: ostr=0, scratch)
    }
}

// One warp per block; 10 sequences per warp (lanes 0-29; 30-31 shadow).
__global__ void __launch_bounds__(32, 16)
k_lstm3(const float* Wih0, const float* Whh0, const float* bih0, const float* bhh0,
        float* buf0, int T0, int nB0, int nW0,
        const float* Wih1, const float* Whh1, const float* bih1, const float* bhh1,
        float* buf1, int T1, int nB1) {
    int warpId = blockIdx.x;
    int lane = threadIdx.x & 31;
    int ln = (lane < 30) ? lane : 29;       // shadow lanes mirror lane 29
    int triple = ln / 3;
    int u = ln - triple * 3;
    int base = triple * 3;

    bool first = (warpId < nW0);
    const float* Wih = first ? Wih0 : Wih1;
    const float* Whh = first ? Whh0 : Whh1;
    const float* bih = first ? bih0 : bih1;
    const float* bhh = first ? bhh0 : bhh1;
    float* bufS = first ? buf0 : buf1;
    int T  = first ? T0 : T1;
    int nB = first ? nB0 : nB1;
    int widx = first ? warpId : (warpId - nW0);

    int b = widx * 10 + triple;
    bool ok = (lane < 30) && (b < nB);
    int bc = (b < nB) ? b : 0;
    float* buf = bufS + (size_t)bc * T * 3;

    float* ob = ok ? (buf + u) : (g_scr + ((warpId & 511) * 32 + lane));
    int ostr = ok ? 3 : 0;

    lstm3(Wih, Whh, bih, bhh, buf, ob, ostr, T, u, base);
}

// ---------------- LayerNorm over (T,H) per batch, write transposed [B,3,T] --
__device__ __forceinline__ void ln_block(const float* __restrict__ in,
                                         const float* __restrict__ w,
                                         const float* __restrict__ bb,
                                         float* __restrict__ out, int T) {
    int n = T * 3;
    float s = 0.f, s2 = 0.f;
    for (int i = threadIdx.x; i < n; i += blockDim.x) {
        float v = in[i];
        s += v;
        s2 = fmaf(v, v, s2);
    }
#pragma unroll
    for (int o = 16; o; o >>= 1) {
        s += __shfl_down_sync(0xffffffffu, s, o);
        s2 += __shfl_down_sync(0xffffffffu, s2, o);
    }
    __shared__ float sh[32], sh2[32];
    int lane = threadIdx.x & 31, wid = threadIdx.x >> 5;
    if (!lane) { sh[wid] = s; sh2[wid] = s2; }
    __syncthreads();
    int nw = blockDim.x >> 5;
    if (wid == 0) {
        s = (lane < nw) ? sh[lane] : 0.f;
        s2 = (lane < nw) ? sh2[lane] : 0.f;
#pragma unroll
        for (int o = 16; o; o >>= 1) {
            s += __shfl_down_sync(0xffffffffu, s, o);
            s2 += __shfl_down_sync(0xffffffffu, s2, o);
        }
        if (!lane) { sh[0] = s; sh2[0] = s2; }
    }
    __syncthreads();
    float mu = sh[0] / (float)n;
    float var = sh2[0] / (float)n - mu * mu;
    float rs = rsqrtf(var + EPSF);
    for (int i = threadIdx.x; i < n; i += blockDim.x) {
        int t = i / 3, c = i % 3;
        float v = fmaf((in[i] - mu) * rs, w[i], bb[i]);
        out[(size_t)c * T + t] = v;
    }
}

__global__ void k_ln(const float* in0, const float* w0, const float* b0, float* out0, int T0,
                     const float* in1, const float* w1, const float* b1, float* out1, int T1) {
    int blk = blockIdx.x;
    if (blk < BB) {
        ln_block(in0 + (size_t)blk * T0 * 3, w0, b0, out0 + (size_t)blk * 3 * T0, T0);
    } else {
        int b = blk - BB;
        ln_block(in1 + (size_t)b * T1 * 3, w1, b1, out1 + (size_t)b * 3 * T1, T1);
    }
}

// ---------------- launch ----------------------------------------------------
extern "C" void kernel_launch(void* const* d_in, const int* in_sizes, int n_in,
                              void* d_out, int out_size) {
    (void)in_sizes; (void)n_in; (void)out_size;
    const float* x      = (const float*)d_in[0];
    const float* mainp  = (const float*)d_in[1];
    const float* sidep  = (const float*)d_in[2];
    const float* conv_w = (const float*)d_in[3];
    const float* conv_b = (const float*)d_in[4];
    const float* bn_w   = (const float*)d_in[5];
    const float* bn_b   = (const float*)d_in[6];
    const float* bn_m   = (const float*)d_in[7];
    const float* bn_v   = (const float*)d_in[8];
    const float* m_Wih = (const float*)d_in[9];
    const float* m_Whh = (const float*)d_in[10];
    const float* m_bih = (const float*)d_in[11];
    const float* m_bhh = (const float*)d_in[12];
    const float* m_lnw = (const float*)d_in[13];
    const float* m_lnb = (const float*)d_in[14];
    const float* s_Wih = (const float*)d_in[15];
    const float* s_Whh = (const float*)d_in[16];
    const float* s_bih = (const float*)d_in[17];
    const float* s_bhh = (const float*)d_in[18];
    const float* s_lnw = (const float*)d_in[19];
    const float* s_lnb = (const float*)d_in[20];
    const float* a_Wih = (const float*)d_in[21];
    const float* a_Whh = (const float*)d_in[22];
    const float* a_bih = (const float*)d_in[23];
    const float* a_bhh = (const float*)d_in[24];
    const float* a_lnw = (const float*)d_in[25];
    const float* a_lnb = (const float*)d_in[26];

    float* out = (float*)d_out;
    float* out_xm  = out;                                   // [B,3,150]
    float* out_xs  = out + (size_t)BB * 3 * TMM;            // [B,3,400]
    float* out_xa  = out + (size_t)BB * 3 * (TMM + LL);     // [B,3,400]

    float* gm0; cudaGetSymbolAddress((void**)&gm0, g_m0);
    float* gs0; cudaGetSymbolAddress((void**)&gs0, g_s0);
    float* ga0; cudaGetSymbolAddress((void**)&ga0, g_a0);

    const int SEQ_PER_WARP = 10;
    int nW_m = (BB + SEQ_PER_WARP - 1) / SEQ_PER_WARP;   // 103
    int nW_s = nW_m;
    int nW_a = nW_m;

    // 1. conv + bn + leakyrelu -> g_xa
    k_conv<<<(BB * LL + 255) / 256, 256>>>(x, conv_w, conv_b, bn_w, bn_b, bn_m, bn_v);
    // 2. xm_pre = xa @ main -> g_m0 [B,150,3]
    k_mm_fwd<<<BB, 160>>>(mainp, gm0, TMM);
    // 3. xs_pre = xa @ side -> g_s0 [B,400,3]
    k_mm_fwd<<<BB, 416>>>(sidep, gs0, LL);
    // 4. LSTM m + s (one warp per block)
    k_lstm3<<<nW_m + nW_s, 32>>>(m_Wih, m_Whh, m_bih, m_bhh, gm0, TMM, BB, nW_m,
                                 s_Wih, s_Whh, s_bih, s_bhh, gs0, LL, BB);
    // 5. LayerNorm m + s -> out (transposed to [B,3,T])
    k_ln<<<2 * BB, 128>>>(gm0, m_lnw, m_lnb, out_xm, TMM,
                          gs0, s_lnw, s_lnb, out_xs, LL);
    // 6. xall_pre = xm @ main^T + xs @ side^T -> g_a0 [B,400,3]
    k_mm_bwd<<<BB, 416>>>(out_xm, out_xs, mainp, sidep);
    // 7. LSTM a
    k_lstm3<<<nW_a, 32>>>(a_Wih, a_Whh, a_bih, a_bhh, ga0, LL, BB, nW_a,
                          a_Wih, a_Whh, a_bih, a_bhh, ga0, LL, 0);
    // 8. LayerNorm a -> out
    k_ln<<<BB, 128>>>(ga0, a_lnw, a_lnb, out_xa, LL,
                      ga0, a_lnw, a_lnb, out_xa, LL);
}

// round 8
// speedup vs baseline: 1.6119x; 1.6119x over previous
#include <cuda_runtime.h>
#include <cstdint>

#define BB 1024
#define LL 400
#define TMM 150
#define EPSF 1e-5f

// ---------------- scratch (device globals; no allocations allowed) ----------
__device__ float g_xa[(size_t)BB * 3 * LL];        // [B,3,400]
__device__ float g_m0[(size_t)BB * TMM * 3];       // [B,150,3]
__device__ float g_s0[(size_t)BB * LL * 3];        // [B,400,3]
__device__ float g_a0[(size_t)BB * LL * 3];        // [B,400,3]

// ---------------- helpers ---------------------------------------------------
__device__ __forceinline__ float tanh_(float x) {
    float y;
    asm("tanh.approx.f32 %0, %1;" : "=f"(y) : "f"(x));
    return y;
}
__device__ __forceinline__ float sigm_(float x) {
    return fmaf(0.5f, tanh_(0.5f * x), 0.5f);
}

// ---------------- conv1d + BN(eval) + LeakyReLU -----------------------------
__global__ void k_conv(const float* __restrict__ x,
                       const float* __restrict__ cw, const float* __restrict__ cb,
                       const float* __restrict__ bw, const float* __restrict__ bb,
                       const float* __restrict__ bm, const float* __restrict__ bv) {
    int idx = blockIdx.x * blockDim.x + threadIdx.x;
    if (idx >= BB * LL) return;
    int b = idx / LL, t = idx % LL;
    const float* xb = x + (size_t)b * 3 * LL;
    float in[3][3];
#pragma unroll
    for (int ci = 0; ci < 3; ci++)
#pragma unroll
        for (int k = 0; k < 3; k++) {
            int tt = t + k - 1;
            in[ci][k] = (tt >= 0 && tt < LL) ? xb[ci * LL + tt] : 0.0f;
        }
#pragma unroll
    for (int co = 0; co < 3; co++) {
        float acc = cb[co];
#pragma unroll
        for (int ci = 0; ci < 3; ci++)
#pragma unroll
            for (int k = 0; k < 3; k++)
                acc = fmaf(cw[(co * 3 + ci) * 3 + k], in[ci][k], acc);
        float sc = bw[co] * rsqrtf(bv[co] + EPSF);
        acc = fmaf(acc - bm[co], sc, bb[co]);
        acc = (acc >= 0.0f) ? acc : 0.01f * acc;
        g_xa[((size_t)b * 3 + co) * LL + t] = acc;
    }
}

// ---------------- forward matmul: out[b,t,c] = sum_k xa[b,c,k]*M[b,k,t] -----
__global__ void k_mm_fwd(const float* __restrict__ M, float* __restrict__ out, int T) {
    int b = blockIdx.x;
    __shared__ float sxa[3][LL];
    for (int i = threadIdx.x; i < 3 * LL; i += blockDim.x)
        sxa[i / LL][i % LL] = g_xa[(size_t)b * 3 * LL + i];
    __syncthreads();
    int t = threadIdx.x;
    if (t >= T) return;
    const float* Mb = M + (size_t)b * LL * T + t;
    float a0 = 0.f, a1 = 0.f, a2 = 0.f;
#pragma unroll 8
    for (int k = 0; k < LL; k++) {
        float mv = Mb[(size_t)k * T];
        a0 = fmaf(sxa[0][k], mv, a0);
        a1 = fmaf(sxa[1][k], mv, a1);
        a2 = fmaf(sxa[2][k], mv, a2);
    }
    float* o = out + ((size_t)b * T + t) * 3;
    o[0] = a0; o[1] = a1; o[2] = a2;
}

// ---------------- fused transpose matmul ------------------------------------
__global__ void k_mm_bwd(const float* __restrict__ xm,   // [B,3,150]
                         const float* __restrict__ xs,   // [B,3,400]
                         const float* __restrict__ M,    // [B,400,150]
                         const float* __restrict__ S) {  // [B,400,400]
    int b = blockIdx.x;
    __shared__ float sm_[3 * 152];
    __shared__ float ss_[3 * LL];
    const float* xmB = xm + (size_t)b * 3 * TMM;
    const float* xsB = xs + (size_t)b * 3 * LL;
    for (int i = threadIdx.x; i < 3 * TMM; i += blockDim.x)
        sm_[(i / TMM) * 152 + (i % TMM)] = xmB[i];
    for (int i = threadIdx.x; i < 3 * LL; i += blockDim.x)
        ss_[i] = xsB[i];
    __syncthreads();
    int t = threadIdx.x;
    if (t >= LL) return;

    float a0 = 0.f, a1 = 0.f, a2 = 0.f;
    const float2* Mr = reinterpret_cast<const float2*>(M + ((size_t)b * LL + t) * TMM);
#pragma unroll 5
    for (int j = 0; j < TMM / 2; j++) {
        float2 v = Mr[j];
        int j0 = 2 * j;
        a0 = fmaf(sm_[0 * 152 + j0], v.x, fmaf(sm_[0 * 152 + j0 + 1], v.y, a0));
        a1 = fmaf(sm_[1 * 152 + j0], v.x, fmaf(sm_[1 * 152 + j0 + 1], v.y, a1));
        a2 = fmaf(sm_[2 * 152 + j0], v.x, fmaf(sm_[2 * 152 + j0 + 1], v.y, a2));
    }
    const float4* Sr = reinterpret_cast<const float4*>(S + ((size_t)b * LL + t) * LL);
#pragma unroll 4
    for (int k = 0; k < LL / 4; k++) {
        float4 v = Sr[k];
        int k0 = 4 * k;
        a0 = fmaf(ss_[k0], v.x, fmaf(ss_[k0 + 1], v.y, fmaf(ss_[k0 + 2], v.z, fmaf(ss_[k0 + 3], v.w, a0))));
        a1 = fmaf(ss_[LL + k0], v.x, fmaf(ss_[LL + k0 + 1], v.y, fmaf(ss_[LL + k0 + 2], v.z, fmaf(ss_[LL + k0 + 3], v.w, a1))));
        a2 = fmaf(ss_[2 * LL + k0], v.x, fmaf(ss_[2 * LL + k0 + 1], v.y, fmaf(ss_[2 * LL + k0 + 2], v.z, fmaf(ss_[2 * LL + k0 + 3], v.w, a2))));
    }
    float* o = g_a0 + ((size_t)b * LL + t) * 3;
    o[0] = a0; o[1] = a1; o[2] = a2;
}

// ---------------- fused 2-layer LSTM + LayerNorm, SMEM-resident -------------
// One warp per block, 10 sequences per warp (3 lanes each; lanes 30/31 shadow
// triple 9). All recurrence traffic is SMEM: input staged in, h2 written back
// in place, LN computed from SMEM, normalized transposed output -> global.
// SMEM per-sequence stride = 3T+1 words: makes the 10 triples hit distinct
// banks (broadcast x-reads conflict-free, h-stores <=2-way).
__global__ void __launch_bounds__(32)
k_lstm_ln(const float* Wih0, const float* Whh0, const float* bih0, const float* bhh0,
          const float* lnw0, const float* lnb0,
          const float* in0, float* out0, int T0, int nB0, int nW0,
          const float* Wih1, const float* Whh1, const float* bih1, const float* bhh1,
          const float* lnw1, const float* lnb1,
          const float* in1, float* out1, int T1, int nB1) {
    __shared__ float sbuf[12016];   // 10 * (3*400+1) = 12010 worst case
    int warpId = blockIdx.x;
    int lane = threadIdx.x & 31;

    bool first = (warpId < nW0);
    const float* Wih = first ? Wih0 : Wih1;
    const float* Whh = first ? Whh0 : Whh1;
    const float* bih = first ? bih0 : bih1;
    const float* bhh = first ? bhh0 : bhh1;
    const float* lnw = first ? lnw0 : lnw1;
    const float* lnb = first ? lnb0 : lnb1;
    const float* inp = first ? in0 : in1;
    float* outp = first ? out0 : out1;
    int T  = first ? T0 : T1;
    int nB = first ? nB0 : nB1;
    int widx = first ? warpId : (warpId - nW0);

    int T3 = 3 * T;
    int stride = T3 + 1;
    int b0 = widx * 10;
    int nv = nB - b0; if (nv > 10) nv = 10;

    // ---- stage inputs into SMEM (coalesced; sequences contiguous in gmem) ----
    const float* src = inp + (size_t)b0 * T3;
    for (int s = 0; s < nv; s++)
        for (int i = lane; i < T3; i += 32)
            sbuf[s * stride + i] = src[s * T3 + i];
    __syncwarp();

    // ---- lane mapping ----
    int ln_ = (lane < 30) ? lane : 29;
    int triple = ln_ / 3;
    int u = ln_ - triple * 3;
    int base = triple * 3;
    float* sb = sbuf + triple * stride;

    // ---- per-lane weights: gates (i,f,g,o) of unit u, layers 0/1 ----
    float wi1[4][3], wh1[4][3], b1[4], wi2[4][3], wh2[4][3], b2[4];
#pragma unroll
    for (int q = 0; q < 4; q++) {
        int gi = q * 3 + u;
#pragma unroll
        for (int v = 0; v < 3; v++) {
            wi1[q][v] = Wih[gi * 3 + v];
            wh1[q][v] = Whh[gi * 3 + v];
            wi2[q][v] = Wih[36 + gi * 3 + v];
            wh2[q][v] = Whh[36 + gi * 3 + v];
        }
        b1[q] = bih[gi] + bhh[gi];
        b2[q] = bih[12 + gi] + bhh[12 + gi];
    }

    // ---- recurrence (all SMEM; warp fully converged; 6 shfls/step) ----
    float c1 = 0.f, c2 = 0.f;
    float h1a = 0.f, h1b = 0.f, h1c = 0.f;
    float h2a = 0.f, h2b = 0.f, h2c = 0.f;

#pragma unroll 2
    for (int t = 0; t < T; t++) {
        float x0 = sb[3 * t], x1 = sb[3 * t + 1], x2 = sb[3 * t + 2];

        // layer-2 recurrent part (off the h1 chain)
        float p2[4];
#pragma unroll
        for (int q = 0; q < 4; q++)
            p2[q] = fmaf(h2a, wh2[q][0], fmaf(h2b, wh2[q][1], fmaf(h2c, wh2[q][2], b2[q])));

        // layer 1
        float g[4];
#pragma unroll
        for (int q = 0; q < 4; q++)
            g[q] = fmaf(x0, wi1[q][0], fmaf(x1, wi1[q][1], fmaf(x2, wi1[q][2],
                   fmaf(h1a, wh1[q][0], fmaf(h1b, wh1[q][1], fmaf(h1c, wh1[q][2], b1[q]))))));
        float si = sigm_(g[0]), sf = sigm_(g[1]), tg = tanh_(g[2]), so = sigm_(g[3]);
        c1 = fmaf(sf, c1, si * tg);
        float h1u = so * tanh_(c1);
        h1a = __shfl_sync(0xffffffffu, h1u, base);
        h1b = __shfl_sync(0xffffffffu, h1u, base + 1);
        h1c = __shfl_sync(0xffffffffu, h1u, base + 2);

        // layer 2
#pragma unroll
        for (int q = 0; q < 4; q++)
            g[q] = fmaf(h1a, wi2[q][0], fmaf(h1b, wi2[q][1], fmaf(h1c, wi2[q][2], p2[q])));
        float si2 = sigm_(g[0]), sf2 = sigm_(g[1]), tg2 = tanh_(g[2]), so2 = sigm_(g[3]);
        c2 = fmaf(sf2, c2, si2 * tg2);
        float h2u = so2 * tanh_(c2);
        h2a = __shfl_sync(0xffffffffu, h2u, base);
        h2b = __shfl_sync(0xffffffffu, h2u, base + 1);
        h2c = __shfl_sync(0xffffffffu, h2u, base + 2);

        sb[3 * t + u] = h2u;   // in-place (x(t) is dead); shadow lanes dup lane 29
    }
    __syncwarp();

    // ---- LayerNorm over (T,3) per sequence, write transposed [3,T] ----
    float s1 = 0.f, s2 = 0.f;
    for (int t = 0; t < T; t++) {
        float v = sb[3 * t + u];
        s1 += v;
        s2 = fmaf(v, v, s2);
    }
    float sa = __shfl_sync(0xffffffffu, s1, base) +
               __shfl_sync(0xffffffffu, s1, base + 1) +
               __shfl_sync(0xffffffffu, s1, base + 2);
    float sq = __shfl_sync(0xffffffffu, s2, base) +
               __shfl_sync(0xffffffffu, s2, base + 1) +
               __shfl_sync(0xffffffffu, s2, base + 2);
    float invn = 1.0f / (float)T3;
    float mu = sa * invn;
    float var = sq * invn - mu * mu;
    float rs = rsqrtf(var + EPSF);

    int b = b0 + triple;
    bool ok = (lane < 30) && (b < nB);
    if (ok) {
        float* op = outp + (size_t)b * T3 + u * T;   // [B,3,T], row u
        for (int t2 = 0; t2 < T / 2; t2++) {
            int t = 2 * t2;
            int i0 = 3 * t + u, i1 = 3 * t + 3 + u;
            float2 v;
            v.x = fmaf((sb[i0] - mu) * rs, lnw[i0], lnb[i0]);
            v.y = fmaf((sb[i1] - mu) * rs, lnw[i1], lnb[i1]);
            *reinterpret_cast<float2*>(op + t) = v;
        }
    }
}

// ---------------- launch ----------------------------------------------------
extern "C" void kernel_launch(void* const* d_in, const int* in_sizes, int n_in,
                              void* d_out, int out_size) {
    (void)in_sizes; (void)n_in; (void)out_size;
    const float* x      = (const float*)d_in[0];
    const float* mainp  = (const float*)d_in[1];
    const float* sidep  = (const float*)d_in[2];
    const float* conv_w = (const float*)d_in[3];
    const float* conv_b = (const float*)d_in[4];
    const float* bn_w   = (const float*)d_in[5];
    const float* bn_b   = (const float*)d_in[6];
    const float* bn_m   = (const float*)d_in[7];
    const float* bn_v   = (const float*)d_in[8];
    const float* m_Wih = (const float*)d_in[9];
    const float* m_Whh = (const float*)d_in[10];
    const float* m_bih = (const float*)d_in[11];
    const float* m_bhh = (const float*)d_in[12];
    const float* m_lnw = (const float*)d_in[13];
    const float* m_lnb = (const float*)d_in[14];
    const float* s_Wih = (const float*)d_in[15];
    const float* s_Whh = (const float*)d_in[16];
    const float* s_bih = (const float*)d_in[17];
    const float* s_bhh = (const float*)d_in[18];
    const float* s_lnw = (const float*)d_in[19];
    const float* s_lnb = (const float*)d_in[20];
    const float* a_Wih = (const float*)d_in[21];
    const float* a_Whh = (const float*)d_in[22];
    const float* a_bih = (const float*)d_in[23];
    const float* a_bhh = (const float*)d_in[24];
    const float* a_lnw = (const float*)d_in[25];
    const float* a_lnb = (const float*)d_in[26];

    float* out = (float*)d_out;
    float* out_xm  = out;                                   // [B,3,150]
    float* out_xs  = out + (size_t)BB * 3 * TMM;            // [B,3,400]
    float* out_xa  = out + (size_t)BB * 3 * (TMM + LL);     // [B,3,400]

    float* gm0; cudaGetSymbolAddress((void**)&gm0, g_m0);
    float* gs0; cudaGetSymbolAddress((void**)&gs0, g_s0);
    float* ga0; cudaGetSymbolAddress((void**)&ga0, g_a0);

    const int SEQ_PER_WARP = 10;
    int nW = (BB + SEQ_PER_WARP - 1) / SEQ_PER_WARP;   // 103

    // 1. conv + bn + leakyrelu -> g_xa
    k_conv<<<(BB * LL + 255) / 256, 256>>>(x, conv_w, conv_b, bn_w, bn_b, bn_m, bn_v);
    // 2. xm_pre = xa @ main -> g_m0 [B,150,3]
    k_mm_fwd<<<BB, 160>>>(mainp, gm0, TMM);
    // 3. xs_pre = xa @ side -> g_s0 [B,400,3]
    k_mm_fwd<<<BB, 416>>>(sidep, gs0, LL);
    // 4. LSTM+LN m & s -> out_xm, out_xs (transposed), no intermediate global
    k_lstm_ln<<<2 * nW, 32>>>(m_Wih, m_Whh, m_bih, m_bhh, m_lnw, m_lnb,
                              gm0, out_xm, TMM, BB, nW,
                              s_Wih, s_Whh, s_bih, s_bhh, s_lnw, s_lnb,
                              gs0, out_xs, LL, BB);
    // 5. xall_pre = xm @ main^T + xs @ side^T -> g_a0 [B,400,3]
    k_mm_bwd<<<BB, 416>>>(out_xm, out_xs, mainp, sidep);
    // 6. LSTM+LN a -> out_xa
    k_lstm_ln<<<nW, 32>>>(a_Wih, a_Whh, a_bih, a_bhh, a_lnw, a_lnb,
                          ga0, out_xa, LL, BB, nW,
                          a_Wih, a_Whh, a_bih, a_bhh, a_lnw, a_lnb,
                          ga0, out_xa, LL, 0);
}

// round 9
// speedup vs baseline: 1.7879x; 1.1092x over previous
#include <cuda_runtime.h>
#include <cstdint>

#define BB 1024
#define LL 400
#define TMM 150
#define EPSF 1e-5f

// ---------------- scratch (device globals; no allocations allowed) ----------
__device__ float g_xa[(size_t)BB * 3 * LL];        // [B,3,400]
__device__ float g_m0[(size_t)BB * TMM * 3];       // [B,150,3]
__device__ float g_s0[(size_t)BB * LL * 3];        // [B,400,3]
__device__ float g_a0[(size_t)BB * LL * 3];        // [B,400,3]

// ---------------- helpers ---------------------------------------------------
__device__ __forceinline__ float tanh_(float x) {
    float y;
    asm("tanh.approx.f32 %0, %1;" : "=f"(y) : "f"(x));
    return y;
}
__device__ __forceinline__ float sigm_(float x) {
    return fmaf(0.5f, tanh_(0.5f * x), 0.5f);
}

// ---------------- conv1d + BN(eval) + LeakyReLU -----------------------------
__global__ void k_conv(const float* __restrict__ x,
                       const float* __restrict__ cw, const float* __restrict__ cb,
                       const float* __restrict__ bw, const float* __restrict__ bb,
                       const float* __restrict__ bm, const float* __restrict__ bv) {
    int idx = blockIdx.x * blockDim.x + threadIdx.x;
    if (idx >= BB * LL) return;
    int b = idx / LL, t = idx % LL;
    const float* xb = x + (size_t)b * 3 * LL;
    float in[3][3];
#pragma unroll
    for (int ci = 0; ci < 3; ci++)
#pragma unroll
        for (int k = 0; k < 3; k++) {
            int tt = t + k - 1;
            in[ci][k] = (tt >= 0 && tt < LL) ? xb[ci * LL + tt] : 0.0f;
        }
#pragma unroll
    for (int co = 0; co < 3; co++) {
        float acc = cb[co];
#pragma unroll
        for (int ci = 0; ci < 3; ci++)
#pragma unroll
            for (int k = 0; k < 3; k++)
                acc = fmaf(cw[(co * 3 + ci) * 3 + k], in[ci][k], acc);
        float sc = bw[co] * rsqrtf(bv[co] + EPSF);
        acc = fmaf(acc - bm[co], sc, bb[co]);
        acc = (acc >= 0.0f) ? acc : 0.01f * acc;
        g_xa[((size_t)b * 3 + co) * LL + t] = acc;
    }
}

// ---------------- forward matmul: out[b,t,c] = sum_k xa[b,c,k]*M[b,k,t] -----
__global__ void k_mm_fwd(const float* __restrict__ M, float* __restrict__ out, int T) {
    int b = blockIdx.x;
    __shared__ float sxa[3][LL];
    for (int i = threadIdx.x; i < 3 * LL; i += blockDim.x)
        sxa[i / LL][i % LL] = g_xa[(size_t)b * 3 * LL + i];
    __syncthreads();
    int t = threadIdx.x;
    if (t >= T) return;
    const float* Mb = M + (size_t)b * LL * T + t;
    float a0 = 0.f, a1 = 0.f, a2 = 0.f;
#pragma unroll 8
    for (int k = 0; k < LL; k++) {
        float mv = Mb[(size_t)k * T];
        a0 = fmaf(sxa[0][k], mv, a0);
        a1 = fmaf(sxa[1][k], mv, a1);
        a2 = fmaf(sxa[2][k], mv, a2);
    }
    float* o = out + ((size_t)b * T + t) * 3;
    o[0] = a0; o[1] = a1; o[2] = a2;
}

// ---------------- fused transpose matmul ------------------------------------
__global__ void k_mm_bwd(const float* __restrict__ xm,   // [B,3,150]
                         const float* __restrict__ xs,   // [B,3,400]
                         const float* __restrict__ M,    // [B,400,150]
                         const float* __restrict__ S) {  // [B,400,400]
    int b = blockIdx.x;
    __shared__ float sm_[3 * 152];
    __shared__ float ss_[3 * LL];
    const float* xmB = xm + (size_t)b * 3 * TMM;
    const float* xsB = xs + (size_t)b * 3 * LL;
    for (int i = threadIdx.x; i < 3 * TMM; i += blockDim.x)
        sm_[(i / TMM) * 152 + (i % TMM)] = xmB[i];
    for (int i = threadIdx.x; i < 3 * LL; i += blockDim.x)
        ss_[i] = xsB[i];
    __syncthreads();
    int t = threadIdx.x;
    if (t >= LL) return;

    float a0 = 0.f, a1 = 0.f, a2 = 0.f;
    const float2* Mr = reinterpret_cast<const float2*>(M + ((size_t)b * LL + t) * TMM);
#pragma unroll 5
    for (int j = 0; j < TMM / 2; j++) {
        float2 v = Mr[j];
        int j0 = 2 * j;
        a0 = fmaf(sm_[0 * 152 + j0], v.x, fmaf(sm_[0 * 152 + j0 + 1], v.y, a0));
        a1 = fmaf(sm_[1 * 152 + j0], v.x, fmaf(sm_[1 * 152 + j0 + 1], v.y, a1));
        a2 = fmaf(sm_[2 * 152 + j0], v.x, fmaf(sm_[2 * 152 + j0 + 1], v.y, a2));
    }
    const float4* Sr = reinterpret_cast<const float4*>(S + ((size_t)b * LL + t) * LL);
#pragma unroll 4
    for (int k = 0; k < LL / 4; k++) {
        float4 v = Sr[k];
        int k0 = 4 * k;
        a0 = fmaf(ss_[k0], v.x, fmaf(ss_[k0 + 1], v.y, fmaf(ss_[k0 + 2], v.z, fmaf(ss_[k0 + 3], v.w, a0))));
        a1 = fmaf(ss_[LL + k0], v.x, fmaf(ss_[LL + k0 + 1], v.y, fmaf(ss_[LL + k0 + 2], v.z, fmaf(ss_[LL + k0 + 3], v.w, a1))));
        a2 = fmaf(ss_[2 * LL + k0], v.x, fmaf(ss_[2 * LL + k0 + 1], v.y, fmaf(ss_[2 * LL + k0 + 2], v.z, fmaf(ss_[2 * LL + k0 + 3], v.w, a2))));
    }
    float* o = g_a0 + ((size_t)b * LL + t) * 3;
    o[0] = a0; o[1] = a1; o[2] = a2;
}

// ---------------- fused 2-layer LSTM + LayerNorm, SMEM-resident -------------
// One warp per block, 5 sequences per warp (3 lanes each; lanes 15-31 shadow
// triple 4). Separate read-only input (sxin) and write-only output (shout)
// SMEM buffers: no store->load aliasing anywhere in the recurrence, so ptxas
// hoists loads and keeps the h-chain short. xc (x·Wih) is computed one step
// ahead and p2 (h2·Whh) before layer 1 — both off the critical h-chain.
#define SEQW 5
#define SSTR(T) (3 * (T) + 5)
__global__ void __launch_bounds__(32)
k_lstm_ln(const float* __restrict__ Wih0, const float* __restrict__ Whh0,
          const float* __restrict__ bih0, const float* __restrict__ bhh0,
          const float* __restrict__ lnw0, const float* __restrict__ lnb0,
          const float* __restrict__ in0, float* __restrict__ out0,
          int T0, int nB0, int nW0,
          const float* __restrict__ Wih1, const float* __restrict__ Whh1,
          const float* __restrict__ bih1, const float* __restrict__ bhh1,
          const float* __restrict__ lnw1, const float* __restrict__ lnb1,
          const float* __restrict__ in1, float* __restrict__ out1,
          int T1, int nB1) {
    __shared__ float sxin[SEQW * (3 * LL + 5)];   // 6025 words
    __shared__ float shout[SEQW * (3 * LL + 5)];  // 6025 words
    int warpId = blockIdx.x;
    int lane = threadIdx.x & 31;

    bool first = (warpId < nW0);
    const float* Wih = first ? Wih0 : Wih1;
    const float* Whh = first ? Whh0 : Whh1;
    const float* bih = first ? bih0 : bih1;
    const float* bhh = first ? bhh0 : bhh1;
    const float* lnw = first ? lnw0 : lnw1;
    const float* lnb = first ? lnb0 : lnb1;
    const float* inp = first ? in0 : in1;
    float* outp = first ? out0 : out1;
    int T  = first ? T0 : T1;
    int nB = first ? nB0 : nB1;
    int widx = first ? warpId : (warpId - nW0);

    int T3 = 3 * T;
    int stride = T3 + 5;                 // odd -> coprime with 32 banks
    int b0 = widx * SEQW;
    int nv = nB - b0; if (nv > SEQW) nv = SEQW;

    // ---- stage inputs into SMEM (coalesced) ----
    const float* src = inp + (size_t)b0 * T3;
    for (int s = 0; s < nv; s++)
        for (int i = lane; i < T3; i += 32)
            sxin[s * stride + i] = src[s * T3 + i];
    __syncwarp();

    // ---- lane mapping: 5 triples, lanes 15-31 shadow triple 4 ----
    int ln_ = (lane < 3 * SEQW) ? lane : (3 * SEQW - 1);
    int triple = ln_ / 3;
    int u = ln_ - triple * 3;
    int base = triple * 3;
    const float* xin = sxin + triple * stride;
    float* hout = shout + triple * stride;

    // ---- per-lane weights: gates (i,f,g,o) of unit u, layers 0/1 ----
    float wi1[4][3], wh1[4][3], b1[4], wi2[4][3], wh2[4][3], b2[4];
#pragma unroll
    for (int q = 0; q < 4; q++) {
        int gi = q * 3 + u;
#pragma unroll
        for (int v = 0; v < 3; v++) {
            wi1[q][v] = Wih[gi * 3 + v];
            wh1[q][v] = Whh[gi * 3 + v];
            wi2[q][v] = Wih[36 + gi * 3 + v];
            wh2[q][v] = Whh[36 + gi * 3 + v];
        }
        b1[q] = bih[gi] + bhh[gi];
        b2[q] = bih[12 + gi] + bhh[12 + gi];
    }

    // ---- recurrence (SMEM in -> SMEM out, zero aliasing) ----
    float c1 = 0.f, c2 = 0.f;
    float h1a = 0.f, h1b = 0.f, h1c = 0.f;
    float h2a = 0.f, h2b = 0.f, h2c = 0.f;

    // prologue: x(0) and its gate contribution
    float nx0 = xin[0], nx1 = xin[1], nx2 = xin[2];
    float xc[4];
#pragma unroll
    for (int q = 0; q < 4; q++)
        xc[q] = fmaf(nx0, wi1[q][0], fmaf(nx1, wi1[q][1], fmaf(nx2, wi1[q][2], b1[q])));

    for (int t = 0; t < T; t++) {
        // prefetch x(t+1) (clamped); read-only buffer -> freely hoistable
        int tn3 = ((t + 1 < T) ? (t + 1) : t) * 3;
        nx0 = xin[tn3]; nx1 = xin[tn3 + 1]; nx2 = xin[tn3 + 2];

        // layer-2 recurrent part (off the h1 chain)
        float p2[4];
#pragma unroll
        for (int q = 0; q < 4; q++)
            p2[q] = fmaf(h2a, wh2[q][0], fmaf(h2b, wh2[q][1], fmaf(h2c, wh2[q][2], b2[q])));

        // ---- layer 1 (on-chain: 3 FMA after h1 shfl) ----
        float g[4];
#pragma unroll
        for (int q = 0; q < 4; q++)
            g[q] = fmaf(h1a, wh1[q][0], fmaf(h1b, wh1[q][1], fmaf(h1c, wh1[q][2], xc[q])));
        float si = sigm_(g[0]), sf = sigm_(g[1]), tg = tanh_(g[2]), so = sigm_(g[3]);
        c1 = fmaf(sf, c1, si * tg);
        float h1u = so * tanh_(c1);
        h1a = __shfl_sync(0xffffffffu, h1u, base);
        h1b = __shfl_sync(0xffffffffu, h1u, base + 1);
        h1c = __shfl_sync(0xffffffffu, h1u, base + 2);

        // next step's x contribution (off-chain)
#pragma unroll
        for (int q = 0; q < 4; q++)
            xc[q] = fmaf(nx0, wi1[q][0], fmaf(nx1, wi1[q][1], fmaf(nx2, wi1[q][2], b1[q])));

        // ---- layer 2 (on-chain: 3 FMA after h1) ----
#pragma unroll
        for (int q = 0; q < 4; q++)
            g[q] = fmaf(h1a, wi2[q][0], fmaf(h1b, wi2[q][1], fmaf(h1c, wi2[q][2], p2[q])));
        float si2 = sigm_(g[0]), sf2 = sigm_(g[1]), tg2 = tanh_(g[2]), so2 = sigm_(g[3]);
        c2 = fmaf(sf2, c2, si2 * tg2);
        float h2u = so2 * tanh_(c2);
        h2a = __shfl_sync(0xffffffffu, h2u, base);
        h2b = __shfl_sync(0xffffffffu, h2u, base + 1);
        h2c = __shfl_sync(0xffffffffu, h2u, base + 2);

        hout[3 * t + u] = h2u;   // write-only buffer (shadow lanes dup lane 14)
    }
    __syncwarp();

    // ---- LayerNorm over (T,3) per sequence, write transposed [3,T] ----
    float s1 = 0.f, s2 = 0.f;
    for (int t = 0; t < T; t++) {
        float v = hout[3 * t + u];
        s1 += v;
        s2 = fmaf(v, v, s2);
    }
    float sa = __shfl_sync(0xffffffffu, s1, base) +
               __shfl_sync(0xffffffffu, s1, base + 1) +
               __shfl_sync(0xffffffffu, s1, base + 2);
    float sq = __shfl_sync(0xffffffffu, s2, base) +
               __shfl_sync(0xffffffffu, s2, base + 1) +
               __shfl_sync(0xffffffffu, s2, base + 2);
    float invn = 1.0f / (float)T3;
    float mu = sa * invn;
    float var = sq * invn - mu * mu;
    float rs = rsqrtf(var + EPSF);

    int b = b0 + triple;
    bool ok = (lane < 3 * SEQW) && (b < nB);
    if (ok) {
        float* op = outp + (size_t)b * T3 + u * T;   // [B,3,T], row u
        for (int t2 = 0; t2 < T / 2; t2++) {
            int t = 2 * t2;
            int i0 = 3 * t + u, i1 = 3 * t + 3 + u;
            float2 v;
            v.x = fmaf((hout[i0] - mu) * rs, lnw[i0], lnb[i0]);
            v.y = fmaf((hout[i1] - mu) * rs, lnw[i1], lnb[i1]);
            *reinterpret_cast<float2*>(op + t) = v;
        }
    }
}

// ---------------- launch ----------------------------------------------------
extern "C" void kernel_launch(void* const* d_in, const int* in_sizes, int n_in,
                              void* d_out, int out_size) {
    (void)in_sizes; (void)n_in; (void)out_size;
    const float* x      = (const float*)d_in[0];
    const float* mainp  = (const float*)d_in[1];
    const float* sidep  = (const float*)d_in[2];
    const float* conv_w = (const float*)d_in[3];
    const float* conv_b = (const float*)d_in[4];
    const float* bn_w   = (const float*)d_in[5];
    const float* bn_b   = (const float*)d_in[6];
    const float* bn_m   = (const float*)d_in[7];
    const float* bn_v   = (const float*)d_in[8];
    const float* m_Wih = (const float*)d_in[9];
    const float* m_Whh = (const float*)d_in[10];
    const float* m_bih = (const float*)d_in[11];
    const float* m_bhh = (const float*)d_in[12];
    const float* m_lnw = (const float*)d_in[13];
    const float* m_lnb = (const float*)d_in[14];
    const float* s_Wih = (const float*)d_in[15];
    const float* s_Whh = (const float*)d_in[16];
    const float* s_bih = (const float*)d_in[17];
    const float* s_bhh = (const float*)d_in[18];
    const float* s_lnw = (const float*)d_in[19];
    const float* s_lnb = (const float*)d_in[20];
    const float* a_Wih = (const float*)d_in[21];
    const float* a_Whh = (const float*)d_in[22];
    const float* a_bih = (const float*)d_in[23];
    const float* a_bhh = (const float*)d_in[24];
    const float* a_lnw = (const float*)d_in[25];
    const float* a_lnb = (const float*)d_in[26];

    float* out = (float*)d_out;
    float* out_xm  = out;                                   // [B,3,150]
    float* out_xs  = out + (size_t)BB * 3 * TMM;            // [B,3,400]
    float* out_xa  = out + (size_t)BB * 3 * (TMM + LL);     // [B,3,400]

    float* gm0; cudaGetSymbolAddress((void**)&gm0, g_m0);
    float* gs0; cudaGetSymbolAddress((void**)&gs0, g_s0);
    float* ga0; cudaGetSymbolAddress((void**)&ga0, g_a0);

    int nW = (BB + SEQW - 1) / SEQW;   // 205

    // 1. conv + bn + leakyrelu -> g_xa
    k_conv<<<(BB * LL + 255) / 256, 256>>>(x, conv_w, conv_b, bn_w, bn_b, bn_m, bn_v);
    // 2. xm_pre = xa @ main -> g_m0 [B,150,3]
    k_mm_fwd<<<BB, 160>>>(mainp, gm0, TMM);
    // 3. xs_pre = xa @ side -> g_s0 [B,400,3]
    k_mm_fwd<<<BB, 416>>>(sidep, gs0, LL);
    // 4. LSTM+LN m & s -> out_xm, out_xs (transposed)
    k_lstm_ln<<<2 * nW, 32>>>(m_Wih, m_Whh, m_bih, m_bhh, m_lnw, m_lnb,
                              gm0, out_xm, TMM, BB, nW,
                              s_Wih, s_Whh, s_bih, s_bhh, s_lnw, s_lnb,
                              gs0, out_xs, LL, BB);
    // 5. xall_pre = xm @ main^T + xs @ side^T -> g_a0 [B,400,3]
    k_mm_bwd<<<BB, 416>>>(out_xm, out_xs, mainp, sidep);
    // 6. LSTM+LN a -> out_xa
    k_lstm_ln<<<nW, 32>>>(a_Wih, a_Whh, a_bih, a_bhh, a_lnw, a_lnb,
                          ga0, out_xa, LL, BB, nW,
                          a_Wih, a_Whh, a_bih, a_bhh, a_lnw, a_lnb,
                          ga0, out_xa, LL, 0);
}